// round 15
// baseline (speedup 1.0000x reference)
#include <cuda_runtime.h>
#include <cuda_fp16.h>
#include <math.h>
#include <stdint.h>

#define CC 192
#define NB1 4096
#define NB2 1024

// ---------------- scratch (device globals; no allocation) ----------------
__device__ float d_freq[48];
__device__ float g_xn[4 * NB1 * CC];
__device__ float g_nb[4 * NB1 * CC];
__device__ float g_sage[4 * NB1 * CC];
__device__ float g_pool[4 * NB2 * CC];
__device__ float g_gdn[4 * NB2 * CC];
__device__ float g_sage2[4 * NB2 * CC];
__device__ float g_pool2[4 * 256 * CC];
__device__ float g_sqn[4 * NB1];
__device__ int   g_idx[4 * NB1 * 9];
__device__ int   g_perm[4 * NB2];
__device__ float g_sv[4 * NB2];
__device__ float g_scores[4 * NB1];
__device__ float g_scal[2];
__device__ __half g_pa[4 * NB1 * CC];
__device__ __half g_pb[4 * NB1 * CC];
__device__ float g_pdist[4 * NB2 * 4 * 9];
__device__ int   g_pidx[4 * NB2 * 4 * 9];
__device__ unsigned long long g_keys[4 * NB1];

// ---------------- helpers (compute_100-portable) ----------------
__device__ __forceinline__ uint32_t smem_u32(const void* p) {
    uint32_t a;
    asm("{ .reg .u64 t; cvta.to.shared.u64 t, %1; cvt.u32.u64 %0, t; }" : "=r"(a) : "l"(p));
    return a;
}
__device__ __forceinline__ void ldsm4(uint32_t* r, uint32_t addr) {
    asm volatile("ldmatrix.sync.aligned.m8n8.x4.shared.b16 {%0,%1,%2,%3}, [%4];"
                 : "=r"(r[0]), "=r"(r[1]), "=r"(r[2]), "=r"(r[3]) : "r"(addr));
}
__device__ __forceinline__ void mma16816(float* d, const uint32_t* a,
                                         uint32_t b0, uint32_t b1) {
    asm volatile("mma.sync.aligned.m16n8k16.row.col.f32.f16.f16.f32 "
                 "{%0,%1,%2,%3}, {%4,%5,%6,%7}, {%8,%9}, {%0,%1,%2,%3};"
                 : "+f"(d[0]), "+f"(d[1]), "+f"(d[2]), "+f"(d[3])
                 : "r"(a[0]), "r"(a[1]), "r"(a[2]), "r"(a[3]), "r"(b0), "r"(b1));
}
__device__ __forceinline__ unsigned long long pk2(float x, float y) {
    unsigned long long r;
    asm("mov.b64 %0, {%1, %2};" : "=l"(r) : "f"(x), "f"(y));
    return r;
}
__device__ __forceinline__ void upk2(unsigned long long v, float& x, float& y) {
    asm("mov.b64 {%0, %1}, %2;" : "=f"(x), "=f"(y) : "l"(v));
}
__device__ __forceinline__ void fma2(unsigned long long& d, unsigned long long a,
                                     unsigned long long b) {
    asm("fma.rn.f32x2 %0, %1, %2, %0;" : "+l"(d) : "l"(a), "l"(b));
}

// ---------------- positional-encoding frequency table ----------------
__global__ void k_freq() {
    int j = threadIdx.x;
    if (j < 48) d_freq[j] = (float)(1.0 / pow(10000.0, (double)(2 * j) / 96.0));
}

// ---------------- add pos-enc, build node features + sq norms ----------------
__global__ void k_prep(const float* __restrict__ x, float* __restrict__ xn,
                       float* __restrict__ sqn) {
    int n = blockIdx.x, b = blockIdx.y, c = threadIdx.x;
    int y = n >> 6, xw = n & 63;
    float v = x[(((size_t)b * CC + c) * 64 + y) * 64 + xw];
    float f, arg;
    if (c < 96) { f = d_freq[c >> 1];        arg = (float)y  * f; }
    else        { f = d_freq[(c - 96) >> 1]; arg = (float)xw * f; }
    v += (c & 1) ? cosf(arg) : sinf(arg);
    xn[((size_t)b * NB1 + n) * CC + c] = v;
    __shared__ float red[192];
    red[c] = v * v;
    __syncthreads();
    if (c < 64) red[c] += red[c + 64] + red[c + 128];
    __syncthreads();
    if (c < 32) {
        float s = red[c] + red[c + 32];
        for (int o = 16; o; o >>= 1) s += __shfl_down_sync(0xffffffffu, s, o);
        if (c == 0) sqn[b * NB1 + n] = s;
    }
}

// ---------------- generic squared-norm ----------------
__global__ void k_sqn(const float* __restrict__ xn, float* __restrict__ sqn, int N) {
    int n = blockIdx.x, b = blockIdx.y, c = threadIdx.x;
    float v = xn[((size_t)b * N + n) * CC + c];
    __shared__ float red[192];
    red[c] = v * v;
    __syncthreads();
    if (c < 64) red[c] += red[c + 64] + red[c + 128];
    __syncthreads();
    if (c < 32) {
        float s = red[c] + red[c + 32];
        for (int o = 16; o; o >>= 1) s += __shfl_down_sync(0xffffffffu, s, o);
        if (c == 0) sqn[b * N + n] = s;
    }
}

// ---------------- 2-way fp16 split ----------------
__global__ void k_split2(const float* __restrict__ xn, __half* __restrict__ pa,
                         __half* __restrict__ pb, int N) {
    size_t i = (((size_t)blockIdx.y * N + blockIdx.x) * CC) + threadIdx.x;
    float v = xn[i];
    __half a = __float2half_rn(v);
    float r = v - __half2float(a);
    pa[i] = a; pb[i] = __float2half_rn(r);
}

// ---------------- mma.sync kNN (R11-best): 128-row tiles ----------------
#define A_STRIDE 400
#define A_PLANE  (128 * A_STRIDE)
#define OFF_B    (2 * A_PLANE)
#define BBUF     (64 * A_STRIDE)
#define OFF_SQ   (OFF_B + 3 * BBUF)
#define KNN_SMEM (OFF_SQ + 512)

__device__ __forceinline__ void issue_b(uint32_t dstBase, const __half* plane,
                                        int colBase, int tid) {
    const char* g = (const char*)(plane + (size_t)colBase * CC);
#pragma unroll
    for (int t = 0; t < 6; t++) {
        int i = tid + t * 256;
        int row = i / 24, j = i - row * 24;
        uint32_t d = dstBase + row * A_STRIDE + j * 16;
        asm volatile("cp.async.cg.shared.global [%0], [%1], 16;"
                     :: "r"(d), "l"(g + row * 384 + j * 16));
    }
    asm volatile("cp.async.commit_group;" ::: "memory");
}

template<int NA>
__device__ __forceinline__ void gemm_group(float (*acc)[4], uint32_t aBase, uint32_t bBase) {
#pragma unroll
    for (int kk = 0; kk < 192; kk += 16) {
        uint32_t bq[4][4];
#pragma unroll
        for (int n2 = 0; n2 < 4; n2++)
            ldsm4(bq[n2], bBase + (n2 << 4) * A_STRIDE + kk * 2);
#pragma unroll
        for (int ap = 0; ap < NA; ap++) {
            uint32_t a[4];
            ldsm4(a, aBase + ap * A_PLANE + kk * 2);
#pragma unroll
            for (int n2 = 0; n2 < 4; n2++) {
                mma16816(acc[2 * n2],     a, bq[n2][0], bq[n2][1]);
                mma16816(acc[2 * n2 + 1], a, bq[n2][2], bq[n2][3]);
            }
        }
    }
}

// grid: (rowTiles128, batch, nparts). nparts==1 writes final indices directly.
__global__ void __launch_bounds__(256, 1)
k_knn_mma(const __half* __restrict__ pa, const __half* __restrict__ pb,
          const float* __restrict__ sqn, float* __restrict__ pdOut,
          int* __restrict__ piOut, int* __restrict__ idxOut, int N, int nparts) {
    extern __shared__ char sm[];
    const uint32_t smb = smem_u32(sm);
    const int tid = threadIdx.x, warp = tid >> 5, lane = tid & 31;
    const int b = blockIdx.y, rowBase = blockIdx.x << 7, part = blockIdx.z;
    const int span = N / nparts, colStart = part * span;
    const __half* P[2] = { pa + (size_t)b * N * CC, pb + (size_t)b * N * CC };
    const float* SQ = sqn + (size_t)b * N;
    float* sqs = (float*)(sm + OFF_SQ);

    issue_b(smb + OFF_B, P[0], colStart, tid);
    issue_b(smb + OFF_B + BBUF, P[1], colStart, tid);

#pragma unroll 1
    for (int p = 0; p < 2; p++) {
        const uint4* gp = (const uint4*)(P[p] + (size_t)rowBase * CC);
        for (int i = tid; i < 128 * 24; i += 256) {
            int row = i / 24, j = i - row * 24;
            *(uint4*)(sm + p * A_PLANE + row * A_STRIDE + j * 16) = gp[i];
        }
    }

    const int strip = warp << 4;
    const int r0 = strip + (lane >> 2);
    const uint32_t aBase = smb + (strip + (lane & 15)) * A_STRIDE + (((uint32_t)lane >> 4) << 4);
    const uint32_t bOff  = ((lane & 7) + ((lane >> 4) << 3)) * A_STRIDE + (((lane >> 3) & 1) << 4);

    const float sr0 = SQ[rowBase + r0], sr1 = SQ[rowBase + r0 + 8];

    float hd0[9], hd1[9]; int hi0[9], hi1[9];
#pragma unroll
    for (int q = 0; q < 9; q++) {
        hd0[q] = 3.4e38f; hi0[q] = 0x7fffffff;
        hd1[q] = 3.4e38f; hi1[q] = 0x7fffffff;
    }

    float acc[8][4];
    const int nsub = span >> 6, steps = nsub * 2;

#pragma unroll 1
    for (int step = 0; step < steps; step++) {
        const int sub = step >> 1, p = step & 1;
        const int colBase = colStart + (sub << 6);
        asm volatile("cp.async.wait_group 1;" ::: "memory");
        __syncthreads();
        {
            int s2 = step + 2;
            if (s2 < steps)
                issue_b(smb + OFF_B + (s2 % 3) * BBUF, P[s2 & 1],
                        colStart + ((s2 >> 1) << 6), tid);
        }
        if (p == 0) {
            if (tid < 64) sqs[(sub & 1) * 64 + tid] = SQ[colBase + tid];
#pragma unroll
            for (int n = 0; n < 8; n++)
#pragma unroll
                for (int j = 0; j < 4; j++) acc[n][j] = 0.f;
        }
        const uint32_t bBase = smb + OFF_B + (step % 3) * BBUF + bOff;
        if (p == 0) {
            gemm_group<2>(acc, aBase, bBase);          // aa + ba
        } else {
            gemm_group<1>(acc, aBase, bBase);          // ab (bb dropped: <=2^-22 rel)
            const float* sq = sqs + (sub & 1) * 64;
#pragma unroll 1
            for (int n = 0; n < 8; n++) {
#pragma unroll
                for (int j = 0; j < 2; j++) {
                    int col = (n << 3) + ((lane & 3) << 1) + j;
                    float sc = sq[col];
                    int gcol = colBase + col;
                    float dv0 = fmaf(-2.f, acc[n][j], sr0 + sc);
                    if (dv0 < hd0[8]) {
                        hd0[8] = dv0; hi0[8] = gcol;
#pragma unroll
                        for (int q = 8; q > 0; q--) {
                            if (hd0[q - 1] > dv0) {
                                float td = hd0[q-1]; hd0[q-1] = hd0[q]; hd0[q] = td;
                                int   ti = hi0[q-1]; hi0[q-1] = hi0[q]; hi0[q] = ti;
                            } else break;
                        }
                    }
                    float dv1 = fmaf(-2.f, acc[n][2 + j], sr1 + sc);
                    if (dv1 < hd1[8]) {
                        hd1[8] = dv1; hi1[8] = gcol;
#pragma unroll
                        for (int q = 8; q > 0; q--) {
                            if (hd1[q - 1] > dv1) {
                                float td = hd1[q-1]; hd1[q-1] = hd1[q]; hd1[q] = td;
                                int   ti = hi1[q-1]; hi1[q-1] = hi1[q]; hi1[q] = ti;
                            } else break;
                        }
                    }
                }
            }
        }
    }

    __syncthreads();
    float* md = (float*)(sm + OFF_B);
    int*   mi = (int*)(sm + OFF_B + 18432);
    const int tp = lane & 3;
#pragma unroll
    for (int q = 0; q < 9; q++) {
        md[(r0 * 4 + tp) * 9 + q] = hd0[q];
        mi[(r0 * 4 + tp) * 9 + q] = hi0[q];
        md[((r0 + 8) * 4 + tp) * 9 + q] = hd1[q];
        mi[((r0 + 8) * 4 + tp) * 9 + q] = hi1[q];
    }
    __syncthreads();
    if (tp == 0) {
#pragma unroll 1
        for (int rr = 0; rr < 2; rr++) {
            int row = r0 + rr * 8;
            int p4[4] = {0, 0, 0, 0};
            size_t obF = ((size_t)b * N + rowBase + row) * 9;
            size_t obP = (((size_t)b * N + rowBase + row) * nparts + part) * 9;
            for (int q = 0; q < 9; q++) {
                float bd_ = 3.5e38f; int bi = 0x7fffffff, bm = 0;
#pragma unroll
                for (int m = 0; m < 4; m++) {
                    if (p4[m] < 9) {
                        float dv = md[(row * 4 + m) * 9 + p4[m]];
                        int   iv = mi[(row * 4 + m) * 9 + p4[m]];
                        if (dv < bd_ || (dv == bd_ && iv < bi)) { bd_ = dv; bi = iv; bm = m; }
                    }
                }
                if (nparts == 1) {
                    idxOut[obF + q] = bi;
                } else {
                    pdOut[obP + q] = bd_;
                    piOut[obP + q] = bi;
                }
                p4[bm]++;
            }
        }
    }
}

// ---------------- merge P per-part lists -> final 9 indices ----------------
__global__ void k_merge(const float* __restrict__ pd, const int* __restrict__ pi,
                        int* __restrict__ idxOut, int N, int P) {
    int row = blockIdx.x * 128 + threadIdx.x, b = blockIdx.y;
    const float* d = pd + ((size_t)b * N + row) * P * 9;
    const int*   ii = pi + ((size_t)b * N + row) * P * 9;
    int pp[4] = {0, 0, 0, 0};
    size_t ob = ((size_t)b * N + row) * 9;
#pragma unroll 1
    for (int q = 0; q < 9; q++) {
        float bd_ = 3.5e38f; int bi = 0x7fffffff, bm = 0;
        for (int m = 0; m < P; m++) {
            float dv = d[m * 9 + pp[m]];
            int   iv = ii[m * 9 + pp[m]];
            if (dv < bd_ || (dv == bd_ && iv < bi)) { bd_ = dv; bi = iv; bm = m; }
        }
        idxOut[ob + q] = bi;
        pp[bm]++;
    }
}

// ---------------- gather + mean over 9 neighbors ----------------
__global__ void k_gather(const float* __restrict__ xn, const int* __restrict__ idx,
                         float* __restrict__ out, int N) {
    __shared__ int sid[9];
    int n = blockIdx.x, b = blockIdx.y, c = threadIdx.x;
    if (c < 9) sid[c] = idx[((size_t)b * N + n) * 9 + c];
    __syncthreads();
    const float* X = xn + (size_t)b * N * CC;
    float s = 0.f;
#pragma unroll
    for (int k = 0; k < 9; k++) s += X[(size_t)sid[k] * CC + c];
    out[((size_t)b * N + n) * CC + c] = s / 9.0f;
}

// ---------------- unified SAGE / GDN GEMM (packed f32x2 FMA) ----------------
template<bool GDN>
__global__ void k_lin(const float* __restrict__ A1, const float* __restrict__ A2,
                      const float* __restrict__ W1, const float* __restrict__ W2,
                      const float* __restrict__ bias, float* __restrict__ out) {
    int rowBase = blockIdx.x << 6, oBase = blockIdx.y << 6;
    __shared__ __align__(16) float A1s[16][68], A2s[16][68], W1s[16][68], W2s[16][68];
    int tid = threadIdx.x, ty = tid >> 4, tx = tid & 15;
    int lr = tid >> 2, lk = (tid & 3) << 2;
    unsigned long long accp[4][2];
#pragma unroll
    for (int i = 0; i < 4; i++) { accp[i][0] = 0ull; accp[i][1] = 0ull; }
    for (int kk = 0; kk < 192; kk += 16) {
        float4 a1 = *(const float4*)(A1 + (size_t)(rowBase + lr) * CC + kk + lk);
        float4 w1 = *(const float4*)(W1 + (size_t)(oBase + lr) * CC + kk + lk);
        float4 a2, w2;
        if (!GDN) {
            a2 = *(const float4*)(A2 + (size_t)(rowBase + lr) * CC + kk + lk);
            w2 = *(const float4*)(W2 + (size_t)(oBase + lr) * CC + kk + lk);
        }
        __syncthreads();
        if (GDN) { a1.x *= a1.x; a1.y *= a1.y; a1.z *= a1.z; a1.w *= a1.w; }
        A1s[lk+0][lr]=a1.x; A1s[lk+1][lr]=a1.y; A1s[lk+2][lr]=a1.z; A1s[lk+3][lr]=a1.w;
        W1s[lk+0][lr]=w1.x; W1s[lk+1][lr]=w1.y; W1s[lk+2][lr]=w1.z; W1s[lk+3][lr]=w1.w;
        if (!GDN) {
            A2s[lk+0][lr]=a2.x; A2s[lk+1][lr]=a2.y; A2s[lk+2][lr]=a2.z; A2s[lk+3][lr]=a2.w;
            W2s[lk+0][lr]=w2.x; W2s[lk+1][lr]=w2.y; W2s[lk+2][lr]=w2.z; W2s[lk+3][lr]=w2.w;
        }
        __syncthreads();
#pragma unroll
        for (int k = 0; k < 16; k++) {
            float4 xa = *(const float4*)&A1s[k][ty << 2];
            const unsigned long long* up = (const unsigned long long*)&W1s[k][tx << 2];
            unsigned long long u01 = up[0], u23 = up[1];
#pragma unroll
            for (int i = 0; i < 4; i++) {
                float av = (i == 0) ? xa.x : (i == 1) ? xa.y : (i == 2) ? xa.z : xa.w;
                unsigned long long aa = pk2(av, av);
                fma2(accp[i][0], aa, u01);
                fma2(accp[i][1], aa, u23);
            }
            if (!GDN) {
                float4 xb = *(const float4*)&A2s[k][ty << 2];
                const unsigned long long* vp = (const unsigned long long*)&W2s[k][tx << 2];
                unsigned long long v01 = vp[0], v23 = vp[1];
#pragma unroll
                for (int i = 0; i < 4; i++) {
                    float bv = (i == 0) ? xb.x : (i == 1) ? xb.y : (i == 2) ? xb.z : xb.w;
                    unsigned long long bb = pk2(bv, bv);
                    fma2(accp[i][0], bb, v01);
                    fma2(accp[i][1], bb, v23);
                }
            }
        }
    }
#pragma unroll
    for (int i = 0; i < 4; i++) {
        float r[4];
        upk2(accp[i][0], r[0], r[1]);
        upk2(accp[i][1], r[2], r[3]);
#pragma unroll
        for (int j = 0; j < 4; j++) {
            int oc = oBase + (tx << 2) + j;
            size_t off = (size_t)(rowBase + (ty << 2) + i) * CC + oc;
            if (GDN) out[off] = A1[off] * rsqrtf(r[j] + bias[oc]);
            else     out[off] = r[j] + bias[oc];
        }
    }
}

// ---------------- ||w|| ----------------
__global__ void k_wnorm(const float* __restrict__ w, float* __restrict__ outp) {
    int c = threadIdx.x;
    __shared__ float red[192];
    float v = w[c];
    red[c] = v * v;
    __syncthreads();
    if (c < 64) red[c] += red[c + 64] + red[c + 128];
    __syncthreads();
    if (c < 32) {
        float s = red[c] + red[c + 32];
        for (int o = 16; o; o >>= 1) s += __shfl_down_sync(0xffffffffu, s, o);
        if (c == 0) *outp = sqrtf(s);
    }
}

// ---------------- pooling scores ----------------
__global__ void k_scores(const float* __restrict__ xn, const float* __restrict__ w,
                         const float* __restrict__ nrm, float* __restrict__ s) {
    int gw = (blockIdx.x << 3) + (threadIdx.x >> 5);
    int lane = threadIdx.x & 31;
    const float* row = xn + (size_t)gw * CC;
    float acc = 0.f;
#pragma unroll
    for (int c = lane; c < CC; c += 32) acc += row[c] * w[c];
    for (int o = 16; o; o >>= 1) acc += __shfl_down_sync(0xffffffffu, acc, o);
    if (!lane) s[gw] = tanhf(acc / nrm[0]);
}

// ---------------- sortA: per-chunk bitonic sort (ascending mapped keys) ----------------
__global__ void k_sortA(const float* __restrict__ s, unsigned long long* __restrict__ keys,
                        int N) {
    extern __shared__ unsigned long long sk[];
    int chunk = blockIdx.x, b = blockIdx.y;
    int M = N >> 2;
    int base = b * N + chunk * M;
    int tid = threadIdx.x, nt = blockDim.x;
    for (int i = tid; i < M; i += nt) {
        unsigned u = __float_as_uint(s[base + i]);
        u = (u & 0x80000000u) ? ~u : (u | 0x80000000u);
        u = ~u;                                          // ascending = score desc, idx asc
        sk[i] = ((unsigned long long)u << 32) | (unsigned)(chunk * M + i);
    }
    __syncthreads();
    for (int k2 = 2; k2 <= M; k2 <<= 1)
        for (int j = k2 >> 1; j > 0; j >>= 1) {
            for (int i = tid; i < M; i += nt) {
                int ixj = i ^ j;
                if (ixj > i) {
                    unsigned long long a = sk[i], c = sk[ixj];
                    bool up = ((i & k2) == 0);
                    if ((a > c) == up) { sk[i] = c; sk[ixj] = a; }
                }
            }
            __syncthreads();
        }
    for (int i = tid; i < M; i += nt) keys[base + i] = sk[i];
}

// ---------------- sortB: rank via binary search across 4 sorted chunks ----------------
__global__ void k_sortB(const unsigned long long* __restrict__ keys,
                        int* __restrict__ perm, float* __restrict__ sv,
                        int N, int KEEP) {
    int b = blockIdx.y;
    int i = blockIdx.x * blockDim.x + threadIdx.x;   // element index in [0, N)
    int M = N >> 2;
    int chunk = i / M, pos = i - chunk * M;
    unsigned long long key = keys[b * N + i];
    int rank = pos;
#pragma unroll
    for (int c = 0; c < 4; c++) {
        if (c == chunk) continue;
        const unsigned long long* L = keys + b * N + c * M;
        int lo = 0, hi = M;
        while (lo < hi) {                             // keys unique -> exact rank
            int mid = (lo + hi) >> 1;
            if (L[mid] < key) lo = mid + 1; else hi = mid;
        }
        rank += lo;
    }
    if (rank < KEEP) {
        unsigned idx = (unsigned)(key & 0xffffffffu);
        unsigned u = ~(unsigned)(key >> 32);
        u = (u & 0x80000000u) ? (u & 0x7fffffffu) : ~u;
        perm[b * KEEP + rank] = (int)idx;
        sv[b * KEEP + rank] = __uint_as_float(u);
    }
}

// ---------------- gather kept nodes, gate by score ----------------
__global__ void k_gatherpool(const float* __restrict__ in, const int* __restrict__ perm,
                             const float* __restrict__ sv, float* __restrict__ out,
                             int N, int KEEP) {
    int i = blockIdx.x, b = blockIdx.y, c = threadIdx.x;
    int p = perm[b * KEEP + i];
    out[((size_t)b * KEEP + i) * CC + c] = in[((size_t)b * N + p) * CC + c] * sv[b * KEEP + i];
}

// ---------------- final NHWC->NCHW ----------------
__global__ void k_final(const float* __restrict__ in, float* __restrict__ out) {
    int n = blockIdx.x, b = blockIdx.y, c = threadIdx.x;
    out[(((size_t)b * CC + c) * 16 + (n >> 4)) * 16 + (n & 15)] =
        in[((size_t)b * 256 + n) * CC + c];
}

// ---------------- launch ----------------
extern "C" void kernel_launch(void* const* d_in, const int* in_sizes, int n_in,
                              void* d_out, int out_size) {
    const float* x     = (const float*)d_in[0];
    const float* W1l   = (const float*)d_in[1];
    const float* b1l   = (const float*)d_in[2];
    const float* W1r   = (const float*)d_in[3];
    const float* p1w   = (const float*)d_in[4];
    const float* gbeta = (const float*)d_in[5];
    const float* ggam  = (const float*)d_in[6];
    const float* W2l   = (const float*)d_in[7];
    const float* b2l   = (const float*)d_in[8];
    const float* W2r   = (const float*)d_in[9];
    const float* p2w   = (const float*)d_in[10];
    float* out = (float*)d_out;

    float *xn, *nb, *sg, *pl, *gd, *sg2, *pl2, *sqn, *sv, *sc, *scal, *pd;
    int *idx, *perm, *pi;
    __half *pa, *pb;
    unsigned long long* keys;
    cudaGetSymbolAddress((void**)&xn,   g_xn);
    cudaGetSymbolAddress((void**)&nb,   g_nb);
    cudaGetSymbolAddress((void**)&sg,   g_sage);
    cudaGetSymbolAddress((void**)&pl,   g_pool);
    cudaGetSymbolAddress((void**)&gd,   g_gdn);
    cudaGetSymbolAddress((void**)&sg2,  g_sage2);
    cudaGetSymbolAddress((void**)&pl2,  g_pool2);
    cudaGetSymbolAddress((void**)&sqn,  g_sqn);
    cudaGetSymbolAddress((void**)&sv,   g_sv);
    cudaGetSymbolAddress((void**)&sc,   g_scores);
    cudaGetSymbolAddress((void**)&scal, g_scal);
    cudaGetSymbolAddress((void**)&idx,  g_idx);
    cudaGetSymbolAddress((void**)&perm, g_perm);
    cudaGetSymbolAddress((void**)&pa,   g_pa);
    cudaGetSymbolAddress((void**)&pb,   g_pb);
    cudaGetSymbolAddress((void**)&pd,   g_pdist);
    cudaGetSymbolAddress((void**)&pi,   g_pidx);
    cudaGetSymbolAddress((void**)&keys, g_keys);

    cudaFuncSetAttribute(k_knn_mma, cudaFuncAttributeMaxDynamicSharedMemorySize, KNN_SMEM);

    k_freq<<<1, 64>>>();

    // ---- stage 1 (N = 4096) ----
    k_prep<<<dim3(NB1, 4), 192>>>(x, xn, sqn);
    k_split2<<<dim3(NB1, 4), 192>>>(xn, pa, pb, NB1);
    k_knn_mma<<<dim3(NB1 / 128, 4, 1), 256, KNN_SMEM>>>(pa, pb, sqn, pd, pi, idx, NB1, 1);
    k_gather<<<dim3(NB1, 4), 192>>>(xn, idx, nb, NB1);
    k_lin<false><<<dim3(4 * NB1 / 64, 3), 256>>>(nb, xn, W1l, W1r, b1l, sg);
    k_wnorm<<<1, 192>>>(p1w, scal);
    k_scores<<<4 * NB1 / 8, 256>>>(sg, p1w, scal, sc);
    k_sortA<<<dim3(4, 4), 256, (NB1 / 4) * 8>>>(sc, keys, NB1);
    k_sortB<<<dim3(NB1 / 256, 4), 256>>>(keys, perm, sv, NB1, NB2);
    k_gatherpool<<<dim3(NB2, 4), 192>>>(sg, perm, sv, pl, NB1, NB2);
    k_lin<true><<<dim3(4 * NB2 / 64, 3), 256>>>(pl, pl, ggam, ggam, gbeta, gd);

    // ---- stage 2 (N = 1024, kNN col-split 4-way + merge) ----
    k_sqn<<<dim3(NB2, 4), 192>>>(gd, sqn, NB2);
    k_split2<<<dim3(NB2, 4), 192>>>(gd, pa, pb, NB2);
    k_knn_mma<<<dim3(NB2 / 128, 4, 4), 256, KNN_SMEM>>>(pa, pb, sqn, pd, pi, idx, NB2, 4);
    k_merge<<<dim3(NB2 / 128, 4), 128>>>(pd, pi, idx, NB2, 4);
    k_gather<<<dim3(NB2, 4), 192>>>(gd, idx, nb, NB2);
    k_lin<false><<<dim3(4 * NB2 / 64, 3), 256>>>(nb, gd, W2l, W2r, b2l, sg2);
    k_wnorm<<<1, 192>>>(p2w, scal + 1);
    k_scores<<<4 * NB2 / 8, 256>>>(sg2, p2w, scal + 1, sc);
    k_sortA<<<dim3(4, 4), 256, (NB2 / 4) * 8>>>(sc, keys, NB2);
    k_sortB<<<dim3(NB2 / 256, 4), 256>>>(keys, perm, sv, NB2, 256);
    k_gatherpool<<<dim3(256, 4), 192>>>(sg2, perm, sv, pl2, NB2, 256);
    k_final<<<dim3(256, 4), 192>>>(pl2, out);
}

// round 16
// speedup vs baseline: 1.0553x; 1.0553x over previous
#include <cuda_runtime.h>
#include <cuda_fp16.h>
#include <math.h>
#include <stdint.h>

#define CC 192
#define NB1 4096
#define NB2 1024

// ---------------- scratch (device globals; no allocation) ----------------
__device__ float d_freq[48];
__device__ float g_xn[4 * NB1 * CC];
__device__ float g_nb[4 * NB1 * CC];
__device__ float g_sage[4 * NB1 * CC];
__device__ float g_pool[4 * NB2 * CC];
__device__ float g_gdn[4 * NB2 * CC];
__device__ float g_sage2[4 * NB2 * CC];
__device__ float g_pool2[4 * 256 * CC];
__device__ float g_sqn[4 * NB1];
__device__ int   g_idx[4 * NB1 * 9];
__device__ int   g_perm[4 * NB2];
__device__ float g_sv[4 * NB2];
__device__ float g_scores[4 * NB1];
__device__ float g_scal[2];
__device__ __half g_pa[4 * NB1 * CC];
__device__ __half g_pb[4 * NB1 * CC];
__device__ float g_pdist[4 * NB2 * 4 * 9];
__device__ int   g_pidx[4 * NB2 * 4 * 9];
__device__ unsigned long long g_keys[4 * NB1];

// ---------------- helpers (compute_100-portable) ----------------
__device__ __forceinline__ uint32_t smem_u32(const void* p) {
    uint32_t a;
    asm("{ .reg .u64 t; cvta.to.shared.u64 t, %1; cvt.u32.u64 %0, t; }" : "=r"(a) : "l"(p));
    return a;
}
__device__ __forceinline__ void ldsm4(uint32_t* r, uint32_t addr) {
    asm volatile("ldmatrix.sync.aligned.m8n8.x4.shared.b16 {%0,%1,%2,%3}, [%4];"
                 : "=r"(r[0]), "=r"(r[1]), "=r"(r[2]), "=r"(r[3]) : "r"(addr));
}
__device__ __forceinline__ void mma16816(float* d, const uint32_t* a,
                                         uint32_t b0, uint32_t b1) {
    asm volatile("mma.sync.aligned.m16n8k16.row.col.f32.f16.f16.f32 "
                 "{%0,%1,%2,%3}, {%4,%5,%6,%7}, {%8,%9}, {%0,%1,%2,%3};"
                 : "+f"(d[0]), "+f"(d[1]), "+f"(d[2]), "+f"(d[3])
                 : "r"(a[0]), "r"(a[1]), "r"(a[2]), "r"(a[3]), "r"(b0), "r"(b1));
}
__device__ __forceinline__ unsigned long long pk2(float x, float y) {
    unsigned long long r;
    asm("mov.b64 %0, {%1, %2};" : "=l"(r) : "f"(x), "f"(y));
    return r;
}
__device__ __forceinline__ void upk2(unsigned long long v, float& x, float& y) {
    asm("mov.b64 {%0, %1}, %2;" : "=f"(x), "=f"(y) : "l"(v));
}
__device__ __forceinline__ void fma2(unsigned long long& d, unsigned long long a,
                                     unsigned long long b) {
    asm("fma.rn.f32x2 %0, %1, %2, %0;" : "+l"(d) : "l"(a), "l"(b));
}

// ---------------- positional-encoding frequency table ----------------
__global__ void k_freq() {
    int j = threadIdx.x;
    if (j < 48) d_freq[j] = (float)(1.0 / pow(10000.0, (double)(2 * j) / 96.0));
}

// ---------------- add pos-enc, build node features + sq norms ----------------
__global__ void k_prep(const float* __restrict__ x, float* __restrict__ xn,
                       float* __restrict__ sqn) {
    int n = blockIdx.x, b = blockIdx.y, c = threadIdx.x;
    int y = n >> 6, xw = n & 63;
    float v = x[(((size_t)b * CC + c) * 64 + y) * 64 + xw];
    float f, arg;
    if (c < 96) { f = d_freq[c >> 1];        arg = (float)y  * f; }
    else        { f = d_freq[(c - 96) >> 1]; arg = (float)xw * f; }
    v += (c & 1) ? cosf(arg) : sinf(arg);
    xn[((size_t)b * NB1 + n) * CC + c] = v;
    __shared__ float red[192];
    red[c] = v * v;
    __syncthreads();
    if (c < 64) red[c] += red[c + 64] + red[c + 128];
    __syncthreads();
    if (c < 32) {
        float s = red[c] + red[c + 32];
        for (int o = 16; o; o >>= 1) s += __shfl_down_sync(0xffffffffu, s, o);
        if (c == 0) sqn[b * NB1 + n] = s;
    }
}

// ---------------- generic squared-norm ----------------
__global__ void k_sqn(const float* __restrict__ xn, float* __restrict__ sqn, int N) {
    int n = blockIdx.x, b = blockIdx.y, c = threadIdx.x;
    float v = xn[((size_t)b * N + n) * CC + c];
    __shared__ float red[192];
    red[c] = v * v;
    __syncthreads();
    if (c < 64) red[c] += red[c + 64] + red[c + 128];
    __syncthreads();
    if (c < 32) {
        float s = red[c] + red[c + 32];
        for (int o = 16; o; o >>= 1) s += __shfl_down_sync(0xffffffffu, s, o);
        if (c == 0) sqn[b * N + n] = s;
    }
}

// ---------------- 2-way fp16 split ----------------
__global__ void k_split2(const float* __restrict__ xn, __half* __restrict__ pa,
                         __half* __restrict__ pb, int N) {
    size_t i = (((size_t)blockIdx.y * N + blockIdx.x) * CC) + threadIdx.x;
    float v = xn[i];
    __half a = __float2half_rn(v);
    float r = v - __half2float(a);
    pa[i] = a; pb[i] = __float2half_rn(r);
}

// ---------------- mma.sync kNN (R11-best): 128-row tiles ----------------
#define A_STRIDE 400
#define A_PLANE  (128 * A_STRIDE)
#define OFF_B    (2 * A_PLANE)
#define BBUF     (64 * A_STRIDE)
#define OFF_SQ   (OFF_B + 3 * BBUF)
#define KNN_SMEM (OFF_SQ + 512)

__device__ __forceinline__ void issue_b(uint32_t dstBase, const __half* plane,
                                        int colBase, int tid) {
    const char* g = (const char*)(plane + (size_t)colBase * CC);
#pragma unroll
    for (int t = 0; t < 6; t++) {
        int i = tid + t * 256;
        int row = i / 24, j = i - row * 24;
        uint32_t d = dstBase + row * A_STRIDE + j * 16;
        asm volatile("cp.async.cg.shared.global [%0], [%1], 16;"
                     :: "r"(d), "l"(g + row * 384 + j * 16));
    }
    asm volatile("cp.async.commit_group;" ::: "memory");
}

template<int NA>
__device__ __forceinline__ void gemm_group(float (*acc)[4], uint32_t aBase, uint32_t bBase) {
#pragma unroll
    for (int kk = 0; kk < 192; kk += 16) {
        uint32_t bq[4][4];
#pragma unroll
        for (int n2 = 0; n2 < 4; n2++)
            ldsm4(bq[n2], bBase + (n2 << 4) * A_STRIDE + kk * 2);
#pragma unroll
        for (int ap = 0; ap < NA; ap++) {
            uint32_t a[4];
            ldsm4(a, aBase + ap * A_PLANE + kk * 2);
#pragma unroll
            for (int n2 = 0; n2 < 4; n2++) {
                mma16816(acc[2 * n2],     a, bq[n2][0], bq[n2][1]);
                mma16816(acc[2 * n2 + 1], a, bq[n2][2], bq[n2][3]);
            }
        }
    }
}

// grid: (rowTiles128, batch, NPARTS). NPARTS==1 writes final indices directly.
template<int NPARTS>
__global__ void __launch_bounds__(256, 1)
k_knn_mma(const __half* __restrict__ pa, const __half* __restrict__ pb,
          const float* __restrict__ sqn, float* __restrict__ pdOut,
          int* __restrict__ piOut, int* __restrict__ idxOut, int N) {
    extern __shared__ char sm[];
    const uint32_t smb = smem_u32(sm);
    const int tid = threadIdx.x, warp = tid >> 5, lane = tid & 31;
    const int b = blockIdx.y, rowBase = blockIdx.x << 7, part = blockIdx.z;
    const int span = N / NPARTS, colStart = part * span;
    const __half* P[2] = { pa + (size_t)b * N * CC, pb + (size_t)b * N * CC };
    const float* SQ = sqn + (size_t)b * N;
    float* sqs = (float*)(sm + OFF_SQ);

    issue_b(smb + OFF_B, P[0], colStart, tid);
    issue_b(smb + OFF_B + BBUF, P[1], colStart, tid);

#pragma unroll 1
    for (int p = 0; p < 2; p++) {
        const uint4* gp = (const uint4*)(P[p] + (size_t)rowBase * CC);
        for (int i = tid; i < 128 * 24; i += 256) {
            int row = i / 24, j = i - row * 24;
            *(uint4*)(sm + p * A_PLANE + row * A_STRIDE + j * 16) = gp[i];
        }
    }

    const int strip = warp << 4;
    const int r0 = strip + (lane >> 2);
    const uint32_t aBase = smb + (strip + (lane & 15)) * A_STRIDE + (((uint32_t)lane >> 4) << 4);
    const uint32_t bOff  = ((lane & 7) + ((lane >> 4) << 3)) * A_STRIDE + (((lane >> 3) & 1) << 4);

    const float sr0 = SQ[rowBase + r0], sr1 = SQ[rowBase + r0 + 8];

    float hd0[9], hd1[9]; int hi0[9], hi1[9];
#pragma unroll
    for (int q = 0; q < 9; q++) {
        hd0[q] = 3.4e38f; hi0[q] = 0x7fffffff;
        hd1[q] = 3.4e38f; hi1[q] = 0x7fffffff;
    }

    float acc[8][4];
    const int nsub = span >> 6, steps = nsub * 2;

#pragma unroll 1
    for (int step = 0; step < steps; step++) {
        const int sub = step >> 1, p = step & 1;
        const int colBase = colStart + (sub << 6);
        asm volatile("cp.async.wait_group 1;" ::: "memory");
        __syncthreads();
        {
            int s2 = step + 2;
            if (s2 < steps)
                issue_b(smb + OFF_B + (s2 % 3) * BBUF, P[s2 & 1],
                        colStart + ((s2 >> 1) << 6), tid);
        }
        if (p == 0) {
            if (tid < 64) sqs[(sub & 1) * 64 + tid] = SQ[colBase + tid];
#pragma unroll
            for (int n = 0; n < 8; n++)
#pragma unroll
                for (int j = 0; j < 4; j++) acc[n][j] = 0.f;
        }
        const uint32_t bBase = smb + OFF_B + (step % 3) * BBUF + bOff;
        if (p == 0) {
            gemm_group<2>(acc, aBase, bBase);          // aa + ba
        } else {
            gemm_group<1>(acc, aBase, bBase);          // ab (bb dropped: <=2^-22 rel)
            const float* sq = sqs + (sub & 1) * 64;
#pragma unroll 1
            for (int n = 0; n < 8; n++) {
#pragma unroll
                for (int j = 0; j < 2; j++) {
                    int col = (n << 3) + ((lane & 3) << 1) + j;
                    float sc = sq[col];
                    int gcol = colBase + col;
                    float dv0 = fmaf(-2.f, acc[n][j], sr0 + sc);
                    if (dv0 < hd0[8]) {
                        hd0[8] = dv0; hi0[8] = gcol;
#pragma unroll
                        for (int q = 8; q > 0; q--) {
                            if (hd0[q - 1] > dv0) {
                                float td = hd0[q-1]; hd0[q-1] = hd0[q]; hd0[q] = td;
                                int   ti = hi0[q-1]; hi0[q-1] = hi0[q]; hi0[q] = ti;
                            } else break;
                        }
                    }
                    float dv1 = fmaf(-2.f, acc[n][2 + j], sr1 + sc);
                    if (dv1 < hd1[8]) {
                        hd1[8] = dv1; hi1[8] = gcol;
#pragma unroll
                        for (int q = 8; q > 0; q--) {
                            if (hd1[q - 1] > dv1) {
                                float td = hd1[q-1]; hd1[q-1] = hd1[q]; hd1[q] = td;
                                int   ti = hi1[q-1]; hi1[q-1] = hi1[q]; hi1[q] = ti;
                            } else break;
                        }
                    }
                }
            }
        }
    }

    __syncthreads();
    float* md = (float*)(sm + OFF_B);
    int*   mi = (int*)(sm + OFF_B + 18432);
    const int tp = lane & 3;
#pragma unroll
    for (int q = 0; q < 9; q++) {
        md[(r0 * 4 + tp) * 9 + q] = hd0[q];
        mi[(r0 * 4 + tp) * 9 + q] = hi0[q];
        md[((r0 + 8) * 4 + tp) * 9 + q] = hd1[q];
        mi[((r0 + 8) * 4 + tp) * 9 + q] = hi1[q];
    }
    __syncthreads();
    if (tp == 0) {
#pragma unroll 1
        for (int rr = 0; rr < 2; rr++) {
            int row = r0 + rr * 8;
            int p4[4] = {0, 0, 0, 0};
            size_t obF = ((size_t)b * N + rowBase + row) * 9;
            size_t obP = (((size_t)b * N + rowBase + row) * NPARTS + part) * 9;
            for (int q = 0; q < 9; q++) {
                float bd_ = 3.5e38f; int bi = 0x7fffffff, bm = 0;
#pragma unroll
                for (int m = 0; m < 4; m++) {
                    if (p4[m] < 9) {
                        float dv = md[(row * 4 + m) * 9 + p4[m]];
                        int   iv = mi[(row * 4 + m) * 9 + p4[m]];
                        if (dv < bd_ || (dv == bd_ && iv < bi)) { bd_ = dv; bi = iv; bm = m; }
                    }
                }
                if (NPARTS == 1) {
                    idxOut[obF + q] = bi;
                } else {
                    pdOut[obP + q] = bd_;
                    piOut[obP + q] = bi;
                }
                p4[bm]++;
            }
        }
    }
}

// ---------------- merge P per-part lists -> final 9 indices ----------------
__global__ void k_merge(const float* __restrict__ pd, const int* __restrict__ pi,
                        int* __restrict__ idxOut, int N, int P) {
    int row = blockIdx.x * 128 + threadIdx.x, b = blockIdx.y;
    const float* d = pd + ((size_t)b * N + row) * P * 9;
    const int*   ii = pi + ((size_t)b * N + row) * P * 9;
    int pp[4] = {0, 0, 0, 0};
    size_t ob = ((size_t)b * N + row) * 9;
#pragma unroll 1
    for (int q = 0; q < 9; q++) {
        float bd_ = 3.5e38f; int bi = 0x7fffffff, bm = 0;
        for (int m = 0; m < P; m++) {
            float dv = d[m * 9 + pp[m]];
            int   iv = ii[m * 9 + pp[m]];
            if (dv < bd_ || (dv == bd_ && iv < bi)) { bd_ = dv; bi = iv; bm = m; }
        }
        idxOut[ob + q] = bi;
        pp[bm]++;
    }
}

// ---------------- gather + mean over 9 neighbors ----------------
__global__ void k_gather(const float* __restrict__ xn, const int* __restrict__ idx,
                         float* __restrict__ out, int N) {
    __shared__ int sid[9];
    int n = blockIdx.x, b = blockIdx.y, c = threadIdx.x;
    if (c < 9) sid[c] = idx[((size_t)b * N + n) * 9 + c];
    __syncthreads();
    const float* X = xn + (size_t)b * N * CC;
    float s = 0.f;
#pragma unroll
    for (int k = 0; k < 9; k++) s += X[(size_t)sid[k] * CC + c];
    out[((size_t)b * N + n) * CC + c] = s / 9.0f;
}

// ---------------- unified SAGE / GDN GEMM (packed f32x2 FMA) ----------------
template<bool GDN>
__global__ void k_lin(const float* __restrict__ A1, const float* __restrict__ A2,
                      const float* __restrict__ W1, const float* __restrict__ W2,
                      const float* __restrict__ bias, float* __restrict__ out) {
    int rowBase = blockIdx.x << 6, oBase = blockIdx.y << 6;
    __shared__ __align__(16) float A1s[16][68], A2s[16][68], W1s[16][68], W2s[16][68];
    int tid = threadIdx.x, ty = tid >> 4, tx = tid & 15;
    int lr = tid >> 2, lk = (tid & 3) << 2;
    unsigned long long accp[4][2];
#pragma unroll
    for (int i = 0; i < 4; i++) { accp[i][0] = 0ull; accp[i][1] = 0ull; }
    for (int kk = 0; kk < 192; kk += 16) {
        float4 a1 = *(const float4*)(A1 + (size_t)(rowBase + lr) * CC + kk + lk);
        float4 w1 = *(const float4*)(W1 + (size_t)(oBase + lr) * CC + kk + lk);
        float4 a2, w2;
        if (!GDN) {
            a2 = *(const float4*)(A2 + (size_t)(rowBase + lr) * CC + kk + lk);
            w2 = *(const float4*)(W2 + (size_t)(oBase + lr) * CC + kk + lk);
        }
        __syncthreads();
        if (GDN) { a1.x *= a1.x; a1.y *= a1.y; a1.z *= a1.z; a1.w *= a1.w; }
        A1s[lk+0][lr]=a1.x; A1s[lk+1][lr]=a1.y; A1s[lk+2][lr]=a1.z; A1s[lk+3][lr]=a1.w;
        W1s[lk+0][lr]=w1.x; W1s[lk+1][lr]=w1.y; W1s[lk+2][lr]=w1.z; W1s[lk+3][lr]=w1.w;
        if (!GDN) {
            A2s[lk+0][lr]=a2.x; A2s[lk+1][lr]=a2.y; A2s[lk+2][lr]=a2.z; A2s[lk+3][lr]=a2.w;
            W2s[lk+0][lr]=w2.x; W2s[lk+1][lr]=w2.y; W2s[lk+2][lr]=w2.z; W2s[lk+3][lr]=w2.w;
        }
        __syncthreads();
#pragma unroll
        for (int k = 0; k < 16; k++) {
            float4 xa = *(const float4*)&A1s[k][ty << 2];
            const unsigned long long* up = (const unsigned long long*)&W1s[k][tx << 2];
            unsigned long long u01 = up[0], u23 = up[1];
#pragma unroll
            for (int i = 0; i < 4; i++) {
                float av = (i == 0) ? xa.x : (i == 1) ? xa.y : (i == 2) ? xa.z : xa.w;
                unsigned long long aa = pk2(av, av);
                fma2(accp[i][0], aa, u01);
                fma2(accp[i][1], aa, u23);
            }
            if (!GDN) {
                float4 xb = *(const float4*)&A2s[k][ty << 2];
                const unsigned long long* vp = (const unsigned long long*)&W2s[k][tx << 2];
                unsigned long long v01 = vp[0], v23 = vp[1];
#pragma unroll
                for (int i = 0; i < 4; i++) {
                    float bv = (i == 0) ? xb.x : (i == 1) ? xb.y : (i == 2) ? xb.z : xb.w;
                    unsigned long long bb = pk2(bv, bv);
                    fma2(accp[i][0], bb, v01);
                    fma2(accp[i][1], bb, v23);
                }
            }
        }
    }
#pragma unroll
    for (int i = 0; i < 4; i++) {
        float r[4];
        upk2(accp[i][0], r[0], r[1]);
        upk2(accp[i][1], r[2], r[3]);
#pragma unroll
        for (int j = 0; j < 4; j++) {
            int oc = oBase + (tx << 2) + j;
            size_t off = (size_t)(rowBase + (ty << 2) + i) * CC + oc;
            if (GDN) out[off] = A1[off] * rsqrtf(r[j] + bias[oc]);
            else     out[off] = r[j] + bias[oc];
        }
    }
}

// ---------------- ||w|| ----------------
__global__ void k_wnorm(const float* __restrict__ w, float* __restrict__ outp) {
    int c = threadIdx.x;
    __shared__ float red[192];
    float v = w[c];
    red[c] = v * v;
    __syncthreads();
    if (c < 64) red[c] += red[c + 64] + red[c + 128];
    __syncthreads();
    if (c < 32) {
        float s = red[c] + red[c + 32];
        for (int o = 16; o; o >>= 1) s += __shfl_down_sync(0xffffffffu, s, o);
        if (c == 0) *outp = sqrtf(s);
    }
}

// ---------------- pooling scores ----------------
__global__ void k_scores(const float* __restrict__ xn, const float* __restrict__ w,
                         const float* __restrict__ nrm, float* __restrict__ s) {
    int gw = (blockIdx.x << 3) + (threadIdx.x >> 5);
    int lane = threadIdx.x & 31;
    const float* row = xn + (size_t)gw * CC;
    float acc = 0.f;
#pragma unroll
    for (int c = lane; c < CC; c += 32) acc += row[c] * w[c];
    for (int o = 16; o; o >>= 1) acc += __shfl_down_sync(0xffffffffu, acc, o);
    if (!lane) s[gw] = tanhf(acc / nrm[0]);
}

// ---------------- sortA: per-chunk bitonic sort (ascending mapped keys) ----------------
__global__ void k_sortA(const float* __restrict__ s, unsigned long long* __restrict__ keys,
                        int N) {
    extern __shared__ unsigned long long sk[];
    int chunk = blockIdx.x, b = blockIdx.y;
    int M = N >> 2;
    int base = b * N + chunk * M;
    int tid = threadIdx.x, nt = blockDim.x;
    for (int i = tid; i < M; i += nt) {
        unsigned u = __float_as_uint(s[base + i]);
        u = (u & 0x80000000u) ? ~u : (u | 0x80000000u);
        u = ~u;
        sk[i] = ((unsigned long long)u << 32) | (unsigned)(chunk * M + i);
    }
    __syncthreads();
    for (int k2 = 2; k2 <= M; k2 <<= 1)
        for (int j = k2 >> 1; j > 0; j >>= 1) {
            for (int i = tid; i < M; i += nt) {
                int ixj = i ^ j;
                if (ixj > i) {
                    unsigned long long a = sk[i], c = sk[ixj];
                    bool up = ((i & k2) == 0);
                    if ((a > c) == up) { sk[i] = c; sk[ixj] = a; }
                }
            }
            __syncthreads();
        }
    for (int i = tid; i < M; i += nt) keys[base + i] = sk[i];
}

// ---------------- sortB: rank via binary search across 4 sorted chunks ----------------
__global__ void k_sortB(const unsigned long long* __restrict__ keys,
                        int* __restrict__ perm, float* __restrict__ sv,
                        int N, int KEEP) {
    int b = blockIdx.y;
    int i = blockIdx.x * blockDim.x + threadIdx.x;
    int M = N >> 2;
    int chunk = i / M, pos = i - chunk * M;
    unsigned long long key = keys[b * N + i];
    int rank = pos;
#pragma unroll
    for (int c = 0; c < 4; c++) {
        if (c == chunk) continue;
        const unsigned long long* L = keys + b * N + c * M;
        int lo = 0, hi = M;
        while (lo < hi) {
            int mid = (lo + hi) >> 1;
            if (L[mid] < key) lo = mid + 1; else hi = mid;
        }
        rank += lo;
    }
    if (rank < KEEP) {
        unsigned idx = (unsigned)(key & 0xffffffffu);
        unsigned u = ~(unsigned)(key >> 32);
        u = (u & 0x80000000u) ? (u & 0x7fffffffu) : ~u;
        perm[b * KEEP + rank] = (int)idx;
        sv[b * KEEP + rank] = __uint_as_float(u);
    }
}

// ---------------- gather kept nodes, gate by score ----------------
__global__ void k_gatherpool(const float* __restrict__ in, const int* __restrict__ perm,
                             const float* __restrict__ sv, float* __restrict__ out,
                             int N, int KEEP) {
    int i = blockIdx.x, b = blockIdx.y, c = threadIdx.x;
    int p = perm[b * KEEP + i];
    out[((size_t)b * KEEP + i) * CC + c] = in[((size_t)b * N + p) * CC + c] * sv[b * KEEP + i];
}

// ---------------- final NHWC->NCHW ----------------
__global__ void k_final(const float* __restrict__ in, float* __restrict__ out) {
    int n = blockIdx.x, b = blockIdx.y, c = threadIdx.x;
    out[(((size_t)b * CC + c) * 16 + (n >> 4)) * 16 + (n & 15)] =
        in[((size_t)b * 256 + n) * CC + c];
}

// ---------------- launch ----------------
extern "C" void kernel_launch(void* const* d_in, const int* in_sizes, int n_in,
                              void* d_out, int out_size) {
    const float* x     = (const float*)d_in[0];
    const float* W1l   = (const float*)d_in[1];
    const float* b1l   = (const float*)d_in[2];
    const float* W1r   = (const float*)d_in[3];
    const float* p1w   = (const float*)d_in[4];
    const float* gbeta = (const float*)d_in[5];
    const float* ggam  = (const float*)d_in[6];
    const float* W2l   = (const float*)d_in[7];
    const float* b2l   = (const float*)d_in[8];
    const float* W2r   = (const float*)d_in[9];
    const float* p2w   = (const float*)d_in[10];
    float* out = (float*)d_out;

    float *xn, *nb, *sg, *pl, *gd, *sg2, *pl2, *sqn, *sv, *sc, *scal, *pd;
    int *idx, *perm, *pi;
    __half *pa, *pb;
    unsigned long long* keys;
    cudaGetSymbolAddress((void**)&xn,   g_xn);
    cudaGetSymbolAddress((void**)&nb,   g_nb);
    cudaGetSymbolAddress((void**)&sg,   g_sage);
    cudaGetSymbolAddress((void**)&pl,   g_pool);
    cudaGetSymbolAddress((void**)&gd,   g_gdn);
    cudaGetSymbolAddress((void**)&sg2,  g_sage2);
    cudaGetSymbolAddress((void**)&pl2,  g_pool2);
    cudaGetSymbolAddress((void**)&sqn,  g_sqn);
    cudaGetSymbolAddress((void**)&sv,   g_sv);
    cudaGetSymbolAddress((void**)&sc,   g_scores);
    cudaGetSymbolAddress((void**)&scal, g_scal);
    cudaGetSymbolAddress((void**)&idx,  g_idx);
    cudaGetSymbolAddress((void**)&perm, g_perm);
    cudaGetSymbolAddress((void**)&pa,   g_pa);
    cudaGetSymbolAddress((void**)&pb,   g_pb);
    cudaGetSymbolAddress((void**)&pd,   g_pdist);
    cudaGetSymbolAddress((void**)&pi,   g_pidx);
    cudaGetSymbolAddress((void**)&keys, g_keys);

    cudaFuncSetAttribute(k_knn_mma<1>, cudaFuncAttributeMaxDynamicSharedMemorySize, KNN_SMEM);
    cudaFuncSetAttribute(k_knn_mma<4>, cudaFuncAttributeMaxDynamicSharedMemorySize, KNN_SMEM);

    k_freq<<<1, 64>>>();

    // ---- stage 1 (N = 4096) ----
    k_prep<<<dim3(NB1, 4), 192>>>(x, xn, sqn);
    k_split2<<<dim3(NB1, 4), 192>>>(xn, pa, pb, NB1);
    k_knn_mma<1><<<dim3(NB1 / 128, 4, 1), 256, KNN_SMEM>>>(pa, pb, sqn, pd, pi, idx, NB1);
    k_gather<<<dim3(NB1, 4), 192>>>(xn, idx, nb, NB1);
    k_lin<false><<<dim3(4 * NB1 / 64, 3), 256>>>(nb, xn, W1l, W1r, b1l, sg);
    k_wnorm<<<1, 192>>>(p1w, scal);
    k_scores<<<4 * NB1 / 8, 256>>>(sg, p1w, scal, sc);
    k_sortA<<<dim3(4, 4), 256, (NB1 / 4) * 8>>>(sc, keys, NB1);
    k_sortB<<<dim3(NB1 / 256, 4), 256>>>(keys, perm, sv, NB1, NB2);
    k_gatherpool<<<dim3(NB2, 4), 192>>>(sg, perm, sv, pl, NB1, NB2);
    k_lin<true><<<dim3(4 * NB2 / 64, 3), 256>>>(pl, pl, ggam, ggam, gbeta, gd);

    // ---- stage 2 (N = 1024, kNN col-split 4-way + merge) ----
    k_sqn<<<dim3(NB2, 4), 192>>>(gd, sqn, NB2);
    k_split2<<<dim3(NB2, 4), 192>>>(gd, pa, pb, NB2);
    k_knn_mma<4><<<dim3(NB2 / 128, 4, 4), 256, KNN_SMEM>>>(pa, pb, sqn, pd, pi, idx, NB2);
    k_merge<<<dim3(NB2 / 128, 4), 128>>>(pd, pi, idx, NB2, 4);
    k_gather<<<dim3(NB2, 4), 192>>>(gd, idx, nb, NB2);
    k_lin<false><<<dim3(4 * NB2 / 64, 3), 256>>>(nb, gd, W2l, W2r, b2l, sg2);
    k_wnorm<<<1, 192>>>(p2w, scal + 1);
    k_scores<<<4 * NB2 / 8, 256>>>(sg2, p2w, scal + 1, sc);
    k_sortA<<<dim3(4, 4), 256, (NB2 / 4) * 8>>>(sc, keys, NB2);
    k_sortB<<<dim3(NB2 / 256, 4), 256>>>(keys, perm, sv, NB2, 256);
    k_gatherpool<<<dim3(256, 4), 192>>>(sg2, perm, sv, pl2, NB2, 256);
    k_final<<<dim3(256, 4), 192>>>(pl2, out);
}

// round 17
// speedup vs baseline: 1.0673x; 1.0114x over previous
#include <cuda_runtime.h>
#include <cuda_fp16.h>
#include <math.h>
#include <stdint.h>

#define CC 192
#define NB1 4096
#define NB2 1024

// ---------------- scratch (device globals; no allocation) ----------------
__device__ float d_freq[48];
__device__ float g_xn[4 * NB1 * CC];
__device__ float g_nb[4 * NB1 * CC];
__device__ float g_sage[4 * NB1 * CC];
__device__ float g_pool[4 * NB2 * CC];
__device__ float g_gdn[4 * NB2 * CC];
__device__ float g_sage2[4 * NB2 * CC];
__device__ float g_sqn[4 * NB1];
__device__ int   g_idx[4 * NB1 * 9];
__device__ int   g_perm[4 * NB2];
__device__ float g_sv[4 * NB2];
__device__ float g_scores[4 * NB1];
__device__ float g_scal[2];
__device__ __half g_pa[4 * NB1 * CC];
__device__ __half g_pb[4 * NB1 * CC];
__device__ float g_pdist[4 * NB2 * 4 * 9];
__device__ int   g_pidx[4 * NB2 * 4 * 9];
__device__ unsigned long long g_keys[4 * NB1];

// ---------------- helpers (compute_100-portable) ----------------
__device__ __forceinline__ uint32_t smem_u32(const void* p) {
    uint32_t a;
    asm("{ .reg .u64 t; cvta.to.shared.u64 t, %1; cvt.u32.u64 %0, t; }" : "=r"(a) : "l"(p));
    return a;
}
__device__ __forceinline__ void ldsm4(uint32_t* r, uint32_t addr) {
    asm volatile("ldmatrix.sync.aligned.m8n8.x4.shared.b16 {%0,%1,%2,%3}, [%4];"
                 : "=r"(r[0]), "=r"(r[1]), "=r"(r[2]), "=r"(r[3]) : "r"(addr));
}
__device__ __forceinline__ void mma16816(float* d, const uint32_t* a,
                                         uint32_t b0, uint32_t b1) {
    asm volatile("mma.sync.aligned.m16n8k16.row.col.f32.f16.f16.f32 "
                 "{%0,%1,%2,%3}, {%4,%5,%6,%7}, {%8,%9}, {%0,%1,%2,%3};"
                 : "+f"(d[0]), "+f"(d[1]), "+f"(d[2]), "+f"(d[3])
                 : "r"(a[0]), "r"(a[1]), "r"(a[2]), "r"(a[3]), "r"(b0), "r"(b1));
}
__device__ __forceinline__ unsigned long long pk2(float x, float y) {
    unsigned long long r;
    asm("mov.b64 %0, {%1, %2};" : "=l"(r) : "f"(x), "f"(y));
    return r;
}
__device__ __forceinline__ void upk2(unsigned long long v, float& x, float& y) {
    asm("mov.b64 {%0, %1}, %2;" : "=f"(x), "=f"(y) : "l"(v));
}
__device__ __forceinline__ void fma2(unsigned long long& d, unsigned long long a,
                                     unsigned long long b) {
    asm("fma.rn.f32x2 %0, %1, %2, %0;" : "+l"(d) : "l"(a), "l"(b));
}

// ---------------- positional-encoding frequency table ----------------
__global__ void k_freq() {
    int j = threadIdx.x;
    if (j < 48) d_freq[j] = (float)(1.0 / pow(10000.0, (double)(2 * j) / 96.0));
}

// ---------------- fused: pos-enc + node feats + sq norm + fp16 split ----------------
__global__ void k_prep(const float* __restrict__ x, float* __restrict__ xn,
                       float* __restrict__ sqn, __half* __restrict__ pa,
                       __half* __restrict__ pb) {
    int n = blockIdx.x, b = blockIdx.y, c = threadIdx.x;
    int y = n >> 6, xw = n & 63;
    float v = x[(((size_t)b * CC + c) * 64 + y) * 64 + xw];
    float f, arg;
    if (c < 96) { f = d_freq[c >> 1];        arg = (float)y  * f; }
    else        { f = d_freq[(c - 96) >> 1]; arg = (float)xw * f; }
    v += (c & 1) ? cosf(arg) : sinf(arg);
    size_t off = ((size_t)b * NB1 + n) * CC + c;
    xn[off] = v;
    __half a = __float2half_rn(v);
    pa[off] = a;
    pb[off] = __float2half_rn(v - __half2float(a));
    __shared__ float red[192];
    red[c] = v * v;
    __syncthreads();
    if (c < 64) red[c] += red[c + 64] + red[c + 128];
    __syncthreads();
    if (c < 32) {
        float s = red[c] + red[c + 32];
        for (int o = 16; o; o >>= 1) s += __shfl_down_sync(0xffffffffu, s, o);
        if (c == 0) sqn[b * NB1 + n] = s;
    }
}

// ---------------- fused: sq norm + fp16 split (stage 2) ----------------
__global__ void k_sqn(const float* __restrict__ xn, float* __restrict__ sqn,
                      __half* __restrict__ pa, __half* __restrict__ pb, int N) {
    int n = blockIdx.x, b = blockIdx.y, c = threadIdx.x;
    size_t off = ((size_t)b * N + n) * CC + c;
    float v = xn[off];
    __half a = __float2half_rn(v);
    pa[off] = a;
    pb[off] = __float2half_rn(v - __half2float(a));
    __shared__ float red[192];
    red[c] = v * v;
    __syncthreads();
    if (c < 64) red[c] += red[c + 64] + red[c + 128];
    __syncthreads();
    if (c < 32) {
        float s = red[c] + red[c + 32];
        for (int o = 16; o; o >>= 1) s += __shfl_down_sync(0xffffffffu, s, o);
        if (c == 0) sqn[b * N + n] = s;
    }
}

// ---------------- mma.sync kNN (R11/R16-best): 128-row tiles ----------------
#define A_STRIDE 400
#define A_PLANE  (128 * A_STRIDE)
#define OFF_B    (2 * A_PLANE)
#define BBUF     (64 * A_STRIDE)
#define OFF_SQ   (OFF_B + 3 * BBUF)
#define KNN_SMEM (OFF_SQ + 512)

__device__ __forceinline__ void issue_b(uint32_t dstBase, const __half* plane,
                                        int colBase, int tid) {
    const char* g = (const char*)(plane + (size_t)colBase * CC);
#pragma unroll
    for (int t = 0; t < 6; t++) {
        int i = tid + t * 256;
        int row = i / 24, j = i - row * 24;
        uint32_t d = dstBase + row * A_STRIDE + j * 16;
        asm volatile("cp.async.cg.shared.global [%0], [%1], 16;"
                     :: "r"(d), "l"(g + row * 384 + j * 16));
    }
    asm volatile("cp.async.commit_group;" ::: "memory");
}

template<int NA>
__device__ __forceinline__ void gemm_group(float (*acc)[4], uint32_t aBase, uint32_t bBase) {
#pragma unroll
    for (int kk = 0; kk < 192; kk += 16) {
        uint32_t bq[4][4];
#pragma unroll
        for (int n2 = 0; n2 < 4; n2++)
            ldsm4(bq[n2], bBase + (n2 << 4) * A_STRIDE + kk * 2);
#pragma unroll
        for (int ap = 0; ap < NA; ap++) {
            uint32_t a[4];
            ldsm4(a, aBase + ap * A_PLANE + kk * 2);
#pragma unroll
            for (int n2 = 0; n2 < 4; n2++) {
                mma16816(acc[2 * n2],     a, bq[n2][0], bq[n2][1]);
                mma16816(acc[2 * n2 + 1], a, bq[n2][2], bq[n2][3]);
            }
        }
    }
}

// grid: (rowTiles128, batch, NPARTS). NPARTS==1 writes final indices directly.
template<int NPARTS>
__global__ void __launch_bounds__(256, 1)
k_knn_mma(const __half* __restrict__ pa, const __half* __restrict__ pb,
          const float* __restrict__ sqn, float* __restrict__ pdOut,
          int* __restrict__ piOut, int* __restrict__ idxOut, int N) {
    extern __shared__ char sm[];
    const uint32_t smb = smem_u32(sm);
    const int tid = threadIdx.x, warp = tid >> 5, lane = tid & 31;
    const int b = blockIdx.y, rowBase = blockIdx.x << 7, part = blockIdx.z;
    const int span = N / NPARTS, colStart = part * span;
    const __half* P[2] = { pa + (size_t)b * N * CC, pb + (size_t)b * N * CC };
    const float* SQ = sqn + (size_t)b * N;
    float* sqs = (float*)(sm + OFF_SQ);

    issue_b(smb + OFF_B, P[0], colStart, tid);
    issue_b(smb + OFF_B + BBUF, P[1], colStart, tid);

#pragma unroll 1
    for (int p = 0; p < 2; p++) {
        const uint4* gp = (const uint4*)(P[p] + (size_t)rowBase * CC);
        for (int i = tid; i < 128 * 24; i += 256) {
            int row = i / 24, j = i - row * 24;
            *(uint4*)(sm + p * A_PLANE + row * A_STRIDE + j * 16) = gp[i];
        }
    }

    const int strip = warp << 4;
    const int r0 = strip + (lane >> 2);
    const uint32_t aBase = smb + (strip + (lane & 15)) * A_STRIDE + (((uint32_t)lane >> 4) << 4);
    const uint32_t bOff  = ((lane & 7) + ((lane >> 4) << 3)) * A_STRIDE + (((lane >> 3) & 1) << 4);

    const float sr0 = SQ[rowBase + r0], sr1 = SQ[rowBase + r0 + 8];

    float hd0[9], hd1[9]; int hi0[9], hi1[9];
#pragma unroll
    for (int q = 0; q < 9; q++) {
        hd0[q] = 3.4e38f; hi0[q] = 0x7fffffff;
        hd1[q] = 3.4e38f; hi1[q] = 0x7fffffff;
    }

    float acc[8][4];
    const int nsub = span >> 6, steps = nsub * 2;

#pragma unroll 1
    for (int step = 0; step < steps; step++) {
        const int sub = step >> 1, p = step & 1;
        const int colBase = colStart + (sub << 6);
        asm volatile("cp.async.wait_group 1;" ::: "memory");
        __syncthreads();
        {
            int s2 = step + 2;
            if (s2 < steps)
                issue_b(smb + OFF_B + (s2 % 3) * BBUF, P[s2 & 1],
                        colStart + ((s2 >> 1) << 6), tid);
        }
        if (p == 0) {
            if (tid < 64) sqs[(sub & 1) * 64 + tid] = SQ[colBase + tid];
#pragma unroll
            for (int n = 0; n < 8; n++)
#pragma unroll
                for (int j = 0; j < 4; j++) acc[n][j] = 0.f;
        }
        const uint32_t bBase = smb + OFF_B + (step % 3) * BBUF + bOff;
        if (p == 0) {
            gemm_group<2>(acc, aBase, bBase);          // aa + ba
        } else {
            gemm_group<1>(acc, aBase, bBase);          // ab (bb dropped: <=2^-22 rel)
            const float* sq = sqs + (sub & 1) * 64;
#pragma unroll 1
            for (int n = 0; n < 8; n++) {
#pragma unroll
                for (int j = 0; j < 2; j++) {
                    int col = (n << 3) + ((lane & 3) << 1) + j;
                    float sc = sq[col];
                    int gcol = colBase + col;
                    float dv0 = fmaf(-2.f, acc[n][j], sr0 + sc);
                    if (dv0 < hd0[8]) {
                        hd0[8] = dv0; hi0[8] = gcol;
#pragma unroll
                        for (int q = 8; q > 0; q--) {
                            if (hd0[q - 1] > dv0) {
                                float td = hd0[q-1]; hd0[q-1] = hd0[q]; hd0[q] = td;
                                int   ti = hi0[q-1]; hi0[q-1] = hi0[q]; hi0[q] = ti;
                            } else break;
                        }
                    }
                    float dv1 = fmaf(-2.f, acc[n][2 + j], sr1 + sc);
                    if (dv1 < hd1[8]) {
                        hd1[8] = dv1; hi1[8] = gcol;
#pragma unroll
                        for (int q = 8; q > 0; q--) {
                            if (hd1[q - 1] > dv1) {
                                float td = hd1[q-1]; hd1[q-1] = hd1[q]; hd1[q] = td;
                                int   ti = hi1[q-1]; hi1[q-1] = hi1[q]; hi1[q] = ti;
                            } else break;
                        }
                    }
                }
            }
        }
    }

    __syncthreads();
    float* md = (float*)(sm + OFF_B);
    int*   mi = (int*)(sm + OFF_B + 18432);
    const int tp = lane & 3;
#pragma unroll
    for (int q = 0; q < 9; q++) {
        md[(r0 * 4 + tp) * 9 + q] = hd0[q];
        mi[(r0 * 4 + tp) * 9 + q] = hi0[q];
        md[((r0 + 8) * 4 + tp) * 9 + q] = hd1[q];
        mi[((r0 + 8) * 4 + tp) * 9 + q] = hi1[q];
    }
    __syncthreads();
    if (tp == 0) {
#pragma unroll 1
        for (int rr = 0; rr < 2; rr++) {
            int row = r0 + rr * 8;
            int p4[4] = {0, 0, 0, 0};
            size_t obF = ((size_t)b * N + rowBase + row) * 9;
            size_t obP = (((size_t)b * N + rowBase + row) * NPARTS + part) * 9;
            for (int q = 0; q < 9; q++) {
                float bd_ = 3.5e38f; int bi = 0x7fffffff, bm = 0;
#pragma unroll
                for (int m = 0; m < 4; m++) {
                    if (p4[m] < 9) {
                        float dv = md[(row * 4 + m) * 9 + p4[m]];
                        int   iv = mi[(row * 4 + m) * 9 + p4[m]];
                        if (dv < bd_ || (dv == bd_ && iv < bi)) { bd_ = dv; bi = iv; bm = m; }
                    }
                }
                if (NPARTS == 1) {
                    idxOut[obF + q] = bi;
                } else {
                    pdOut[obP + q] = bd_;
                    piOut[obP + q] = bi;
                }
                p4[bm]++;
            }
        }
    }
}

// ---------------- merge P per-part lists -> final 9 indices ----------------
__global__ void k_merge(const float* __restrict__ pd, const int* __restrict__ pi,
                        int* __restrict__ idxOut, int N, int P) {
    int row = blockIdx.x * 128 + threadIdx.x, b = blockIdx.y;
    const float* d = pd + ((size_t)b * N + row) * P * 9;
    const int*   ii = pi + ((size_t)b * N + row) * P * 9;
    int pp[4] = {0, 0, 0, 0};
    size_t ob = ((size_t)b * N + row) * 9;
#pragma unroll 1
    for (int q = 0; q < 9; q++) {
        float bd_ = 3.5e38f; int bi = 0x7fffffff, bm = 0;
        for (int m = 0; m < P; m++) {
            float dv = d[m * 9 + pp[m]];
            int   iv = ii[m * 9 + pp[m]];
            if (dv < bd_ || (dv == bd_ && iv < bi)) { bd_ = dv; bi = iv; bm = m; }
        }
        idxOut[ob + q] = bi;
        pp[bm]++;
    }
}

// ---------------- gather + mean over 9 neighbors ----------------
__global__ void k_gather(const float* __restrict__ xn, const int* __restrict__ idx,
                         float* __restrict__ out, int N) {
    __shared__ int sid[9];
    int n = blockIdx.x, b = blockIdx.y, c = threadIdx.x;
    if (c < 9) sid[c] = idx[((size_t)b * N + n) * 9 + c];
    __syncthreads();
    const float* X = xn + (size_t)b * N * CC;
    float s = 0.f;
#pragma unroll
    for (int k = 0; k < 9; k++) s += X[(size_t)sid[k] * CC + c];
    out[((size_t)b * N + n) * CC + c] = s / 9.0f;
}

// ---------------- unified SAGE / GDN GEMM (packed f32x2 FMA) ----------------
template<bool GDN>
__global__ void k_lin(const float* __restrict__ A1, const float* __restrict__ A2,
                      const float* __restrict__ W1, const float* __restrict__ W2,
                      const float* __restrict__ bias, float* __restrict__ out) {
    int rowBase = blockIdx.x << 6, oBase = blockIdx.y << 6;
    __shared__ __align__(16) float A1s[16][68], A2s[16][68], W1s[16][68], W2s[16][68];
    int tid = threadIdx.x, ty = tid >> 4, tx = tid & 15;
    int lr = tid >> 2, lk = (tid & 3) << 2;
    unsigned long long accp[4][2];
#pragma unroll
    for (int i = 0; i < 4; i++) { accp[i][0] = 0ull; accp[i][1] = 0ull; }
    for (int kk = 0; kk < 192; kk += 16) {
        float4 a1 = *(const float4*)(A1 + (size_t)(rowBase + lr) * CC + kk + lk);
        float4 w1 = *(const float4*)(W1 + (size_t)(oBase + lr) * CC + kk + lk);
        float4 a2, w2;
        if (!GDN) {
            a2 = *(const float4*)(A2 + (size_t)(rowBase + lr) * CC + kk + lk);
            w2 = *(const float4*)(W2 + (size_t)(oBase + lr) * CC + kk + lk);
        }
        __syncthreads();
        if (GDN) { a1.x *= a1.x; a1.y *= a1.y; a1.z *= a1.z; a1.w *= a1.w; }
        A1s[lk+0][lr]=a1.x; A1s[lk+1][lr]=a1.y; A1s[lk+2][lr]=a1.z; A1s[lk+3][lr]=a1.w;
        W1s[lk+0][lr]=w1.x; W1s[lk+1][lr]=w1.y; W1s[lk+2][lr]=w1.z; W1s[lk+3][lr]=w1.w;
        if (!GDN) {
            A2s[lk+0][lr]=a2.x; A2s[lk+1][lr]=a2.y; A2s[lk+2][lr]=a2.z; A2s[lk+3][lr]=a2.w;
            W2s[lk+0][lr]=w2.x; W2s[lk+1][lr]=w2.y; W2s[lk+2][lr]=w2.z; W2s[lk+3][lr]=w2.w;
        }
        __syncthreads();
#pragma unroll
        for (int k = 0; k < 16; k++) {
            float4 xa = *(const float4*)&A1s[k][ty << 2];
            const unsigned long long* up = (const unsigned long long*)&W1s[k][tx << 2];
            unsigned long long u01 = up[0], u23 = up[1];
#pragma unroll
            for (int i = 0; i < 4; i++) {
                float av = (i == 0) ? xa.x : (i == 1) ? xa.y : (i == 2) ? xa.z : xa.w;
                unsigned long long aa = pk2(av, av);
                fma2(accp[i][0], aa, u01);
                fma2(accp[i][1], aa, u23);
            }
            if (!GDN) {
                float4 xb = *(const float4*)&A2s[k][ty << 2];
                const unsigned long long* vp = (const unsigned long long*)&W2s[k][tx << 2];
                unsigned long long v01 = vp[0], v23 = vp[1];
#pragma unroll
                for (int i = 0; i < 4; i++) {
                    float bv = (i == 0) ? xb.x : (i == 1) ? xb.y : (i == 2) ? xb.z : xb.w;
                    unsigned long long bb = pk2(bv, bv);
                    fma2(accp[i][0], bb, v01);
                    fma2(accp[i][1], bb, v23);
                }
            }
        }
    }
#pragma unroll
    for (int i = 0; i < 4; i++) {
        float r[4];
        upk2(accp[i][0], r[0], r[1]);
        upk2(accp[i][1], r[2], r[3]);
#pragma unroll
        for (int j = 0; j < 4; j++) {
            int oc = oBase + (tx << 2) + j;
            size_t off = (size_t)(rowBase + (ty << 2) + i) * CC + oc;
            if (GDN) out[off] = A1[off] * rsqrtf(r[j] + bias[oc]);
            else     out[off] = r[j] + bias[oc];
        }
    }
}

// ---------------- ||w|| ----------------
__global__ void k_wnorm(const float* __restrict__ w, float* __restrict__ outp) {
    int c = threadIdx.x;
    __shared__ float red[192];
    float v = w[c];
    red[c] = v * v;
    __syncthreads();
    if (c < 64) red[c] += red[c + 64] + red[c + 128];
    __syncthreads();
    if (c < 32) {
        float s = red[c] + red[c + 32];
        for (int o = 16; o; o >>= 1) s += __shfl_down_sync(0xffffffffu, s, o);
        if (c == 0) *outp = sqrtf(s);
    }
}

// ---------------- pooling scores ----------------
__global__ void k_scores(const float* __restrict__ xn, const float* __restrict__ w,
                         const float* __restrict__ nrm, float* __restrict__ s) {
    int gw = (blockIdx.x << 3) + (threadIdx.x >> 5);
    int lane = threadIdx.x & 31;
    const float* row = xn + (size_t)gw * CC;
    float acc = 0.f;
#pragma unroll
    for (int c = lane; c < CC; c += 32) acc += row[c] * w[c];
    for (int o = 16; o; o >>= 1) acc += __shfl_down_sync(0xffffffffu, acc, o);
    if (!lane) s[gw] = tanhf(acc / nrm[0]);
}

// ---------------- sortA: per-chunk bitonic sort (ascending mapped keys) ----------------
__global__ void k_sortA(const float* __restrict__ s, unsigned long long* __restrict__ keys,
                        int N) {
    extern __shared__ unsigned long long sk[];
    int chunk = blockIdx.x, b = blockIdx.y;
    int M = N >> 2;
    int base = b * N + chunk * M;
    int tid = threadIdx.x, nt = blockDim.x;
    for (int i = tid; i < M; i += nt) {
        unsigned u = __float_as_uint(s[base + i]);
        u = (u & 0x80000000u) ? ~u : (u | 0x80000000u);
        u = ~u;
        sk[i] = ((unsigned long long)u << 32) | (unsigned)(chunk * M + i);
    }
    __syncthreads();
    for (int k2 = 2; k2 <= M; k2 <<= 1)
        for (int j = k2 >> 1; j > 0; j >>= 1) {
            for (int i = tid; i < M; i += nt) {
                int ixj = i ^ j;
                if (ixj > i) {
                    unsigned long long a = sk[i], c = sk[ixj];
                    bool up = ((i & k2) == 0);
                    if ((a > c) == up) { sk[i] = c; sk[ixj] = a; }
                }
            }
            __syncthreads();
        }
    for (int i = tid; i < M; i += nt) keys[base + i] = sk[i];
}

// ---------------- sortB: rank via binary search across 4 sorted chunks ----------------
__global__ void k_sortB(const unsigned long long* __restrict__ keys,
                        int* __restrict__ perm, float* __restrict__ sv,
                        int N, int KEEP) {
    int b = blockIdx.y;
    int i = blockIdx.x * blockDim.x + threadIdx.x;
    int M = N >> 2;
    int chunk = i / M, pos = i - chunk * M;
    unsigned long long key = keys[b * N + i];
    int rank = pos;
#pragma unroll
    for (int c = 0; c < 4; c++) {
        if (c == chunk) continue;
        const unsigned long long* L = keys + b * N + c * M;
        int lo = 0, hi = M;
        while (lo < hi) {
            int mid = (lo + hi) >> 1;
            if (L[mid] < key) lo = mid + 1; else hi = mid;
        }
        rank += lo;
    }
    if (rank < KEEP) {
        unsigned idx = (unsigned)(key & 0xffffffffu);
        unsigned u = ~(unsigned)(key >> 32);
        u = (u & 0x80000000u) ? (u & 0x7fffffffu) : ~u;
        perm[b * KEEP + rank] = (int)idx;
        sv[b * KEEP + rank] = __uint_as_float(u);
    }
}

// ---------------- gather kept nodes, gate by score ----------------
__global__ void k_gatherpool(const float* __restrict__ in, const int* __restrict__ perm,
                             const float* __restrict__ sv, float* __restrict__ out,
                             int N, int KEEP) {
    int i = blockIdx.x, b = blockIdx.y, c = threadIdx.x;
    int p = perm[b * KEEP + i];
    out[((size_t)b * KEEP + i) * CC + c] = in[((size_t)b * N + p) * CC + c] * sv[b * KEEP + i];
}

// ---------------- fused stage-2 gatherpool + NHWC->NCHW writeout ----------------
__global__ void k_gatherpool_final(const float* __restrict__ in, const int* __restrict__ perm,
                                   const float* __restrict__ sv, float* __restrict__ out,
                                   int N, int KEEP) {
    int i = blockIdx.x, b = blockIdx.y, c = threadIdx.x;
    int p = perm[b * KEEP + i];
    float v = in[((size_t)b * N + p) * CC + c] * sv[b * KEEP + i];
    out[(((size_t)b * CC + c) * 16 + (i >> 4)) * 16 + (i & 15)] = v;
}

// ---------------- launch ----------------
extern "C" void kernel_launch(void* const* d_in, const int* in_sizes, int n_in,
                              void* d_out, int out_size) {
    const float* x     = (const float*)d_in[0];
    const float* W1l   = (const float*)d_in[1];
    const float* b1l   = (const float*)d_in[2];
    const float* W1r   = (const float*)d_in[3];
    const float* p1w   = (const float*)d_in[4];
    const float* gbeta = (const float*)d_in[5];
    const float* ggam  = (const float*)d_in[6];
    const float* W2l   = (const float*)d_in[7];
    const float* b2l   = (const float*)d_in[8];
    const float* W2r   = (const float*)d_in[9];
    const float* p2w   = (const float*)d_in[10];
    float* out = (float*)d_out;

    float *xn, *nb, *sg, *pl, *gd, *sg2, *sqn, *sv, *sc, *scal, *pd;
    int *idx, *perm, *pi;
    __half *pa, *pb;
    unsigned long long* keys;
    cudaGetSymbolAddress((void**)&xn,   g_xn);
    cudaGetSymbolAddress((void**)&nb,   g_nb);
    cudaGetSymbolAddress((void**)&sg,   g_sage);
    cudaGetSymbolAddress((void**)&pl,   g_pool);
    cudaGetSymbolAddress((void**)&gd,   g_gdn);
    cudaGetSymbolAddress((void**)&sg2,  g_sage2);
    cudaGetSymbolAddress((void**)&sqn,  g_sqn);
    cudaGetSymbolAddress((void**)&sv,   g_sv);
    cudaGetSymbolAddress((void**)&sc,   g_scores);
    cudaGetSymbolAddress((void**)&scal, g_scal);
    cudaGetSymbolAddress((void**)&idx,  g_idx);
    cudaGetSymbolAddress((void**)&perm, g_perm);
    cudaGetSymbolAddress((void**)&pa,   g_pa);
    cudaGetSymbolAddress((void**)&pb,   g_pb);
    cudaGetSymbolAddress((void**)&pd,   g_pdist);
    cudaGetSymbolAddress((void**)&pi,   g_pidx);
    cudaGetSymbolAddress((void**)&keys, g_keys);

    cudaFuncSetAttribute(k_knn_mma<1>, cudaFuncAttributeMaxDynamicSharedMemorySize, KNN_SMEM);
    cudaFuncSetAttribute(k_knn_mma<4>, cudaFuncAttributeMaxDynamicSharedMemorySize, KNN_SMEM);

    k_freq<<<1, 64>>>();

    // ---- stage 1 (N = 4096) ----
    k_prep<<<dim3(NB1, 4), 192>>>(x, xn, sqn, pa, pb);
    k_knn_mma<1><<<dim3(NB1 / 128, 4, 1), 256, KNN_SMEM>>>(pa, pb, sqn, pd, pi, idx, NB1);
    k_gather<<<dim3(NB1, 4), 192>>>(xn, idx, nb, NB1);
    k_lin<false><<<dim3(4 * NB1 / 64, 3), 256>>>(nb, xn, W1l, W1r, b1l, sg);
    k_wnorm<<<1, 192>>>(p1w, scal);
    k_scores<<<4 * NB1 / 8, 256>>>(sg, p1w, scal, sc);
    k_sortA<<<dim3(4, 4), 256, (NB1 / 4) * 8>>>(sc, keys, NB1);
    k_sortB<<<dim3(NB1 / 256, 4), 256>>>(keys, perm, sv, NB1, NB2);
    k_gatherpool<<<dim3(NB2, 4), 192>>>(sg, perm, sv, pl, NB1, NB2);
    k_lin<true><<<dim3(4 * NB2 / 64, 3), 256>>>(pl, pl, ggam, ggam, gbeta, gd);

    // ---- stage 2 (N = 1024, kNN col-split 4-way + merge) ----
    k_sqn<<<dim3(NB2, 4), 192>>>(gd, sqn, pa, pb, NB2);
    k_knn_mma<4><<<dim3(NB2 / 128, 4, 4), 256, KNN_SMEM>>>(pa, pb, sqn, pd, pi, idx, NB2);
    k_merge<<<dim3(NB2 / 128, 4), 128>>>(pd, pi, idx, NB2, 4);
    k_gather<<<dim3(NB2, 4), 192>>>(gd, idx, nb, NB2);
    k_lin<false><<<dim3(4 * NB2 / 64, 3), 256>>>(nb, gd, W2l, W2r, b2l, sg2);
    k_wnorm<<<1, 192>>>(p2w, scal + 1);
    k_scores<<<4 * NB2 / 8, 256>>>(sg2, p2w, scal + 1, sc);
    k_sortA<<<dim3(4, 4), 256, (NB2 / 4) * 8>>>(sc, keys, NB2);
    k_sortB<<<dim3(NB2 / 256, 4), 256>>>(keys, perm, sv, NB2, 256);
    k_gatherpool_final<<<dim3(256, 4), 192>>>(sg2, perm, sv, out, NB2, 256);
}